// round 16
// baseline (speedup 1.0000x reference)
#include <cuda_runtime.h>
#include <cstddef>

// Involution (B=8, H=W=192, C=64, G=4, K=3, R=4 -> cr=16)
// R16: R15 (32x16 tile, 128 thr, 4 vertical px/thread, channel-split smem,
// fma.rn.f32x2 math, w2/b2 smem, w1/b1 packed const) + plane-pipelined
// second-half reload: after phase-D pass0 finishes plane u, its smem slot is
// reloaded with channel-plane 8+u via cp.async overlapped with remaining
// pass0 compute. Only the last plane's transfer tail is exposed.

#define HH 192
#define WW 192
#define CC 64
#define CR 16
#define TAPS 9

typedef unsigned long long u64;

constexpr int TW = 16;
constexpr int TH = 32;
constexpr int HW = 18;
constexpr int HT = 34;
constexpr int NPX = HT * HW;                          // 612 halo pixels
constexpr int PSTR = 9;                               // f4 per pixel (8 data + 1 pad)
constexpr int TILE_F4 = NPX * PSTR;                   // 5508
constexpr int W2_F4 = 144;
constexpr int B2_F4 = 9;
constexpr int SMEM_BYTES = (TILE_F4 + W2_F4 + B2_F4) * 16;  // 90576 B

struct ConstW {
    u64 w1p[16][8][4];   // [c4][dpair][cc], BN folded, packed d-pairs
    u64 b1p[8];          // packed BN-folded bias pairs
};
__constant__ ConstW cW;

struct Scratch {
    ConstW c;
    float4 w2[144];      // [d=16][tap=9], f4 over 4 groups
    float4 b2[9];
};
__device__ Scratch scratchW;

__device__ __forceinline__ u64 pack2(float a, float b) {
    u64 r; asm("mov.b64 %0, {%1, %2};" : "=l"(r) : "f"(a), "f"(b)); return r;
}
__device__ __forceinline__ u64 dup2(float v) {
    u64 r; asm("mov.b64 %0, {%1, %1};" : "=l"(r) : "f"(v)); return r;
}
__device__ __forceinline__ float2 unpk(u64 p) {
    float2 f; asm("mov.b64 {%0, %1}, %2;" : "=f"(f.x), "=f"(f.y) : "l"(p)); return f;
}
__device__ __forceinline__ u64 fma2(u64 a, u64 b, u64 c) {
    u64 r; asm("fma.rn.f32x2 %0, %1, %2, %3;" : "=l"(r) : "l"(a), "l"(b), "l"(c)); return r;
}

__global__ void involution_prep_kernel(const float* __restrict__ w1,
                                       const float* __restrict__ b1,
                                       const float* __restrict__ gamma,
                                       const float* __restrict__ beta,
                                       const float* __restrict__ mean,
                                       const float* __restrict__ var,
                                       const float* __restrict__ w2,
                                       const float* __restrict__ b2) {
    __shared__ float s[16];
    int tid = threadIdx.x;   // 256 threads
    if (tid < 16) {
        float sc = gamma[tid] * rsqrtf(var[tid] + 1e-3f);
        s[tid] = sc;
    }
    __syncthreads();
    if (tid < 8) {
        float a = (b1[2 * tid]     - mean[2 * tid])     * s[2 * tid]     + beta[2 * tid];
        float b = (b1[2 * tid + 1] - mean[2 * tid + 1]) * s[2 * tid + 1] + beta[2 * tid + 1];
        scratchW.c.b1p[tid] = pack2(a, b);
    }
    for (int i = tid; i < 512; i += 256) {
        int c4 = i >> 5;
        int dp = (i >> 2) & 7;
        int cc = i & 3;
        int c  = 4 * c4 + cc;
        scratchW.c.w1p[c4][dp][cc] = pack2(w1[c * CR + 2 * dp]     * s[2 * dp],
                                           w1[c * CR + 2 * dp + 1] * s[2 * dp + 1]);
    }
    if (tid < 144) scratchW.w2[tid] = ((const float4*)w2)[tid];
    if (tid < 9)   scratchW.b2[tid] = ((const float4*)b2)[tid];
}

__device__ __forceinline__ void cp16(unsigned dst, const void* src, int sz) {
    asm volatile("cp.async.cg.shared.global [%0], [%1], 16, %2;"
                 :: "r"(dst), "l"(src), "r"(sz) : "memory");
}

__global__ __launch_bounds__(128, 2)
void involution_fused_kernel(const float* __restrict__ x,
                             float* __restrict__ out) {
    extern __shared__ float4 sm4[];
    float4* tile4 = sm4;                      // [612 px][9 f4]
    float4* w2s   = sm4 + TILE_F4;            // [144]
    float4* b2s   = w2s + W2_F4;              // [9]

    const int tid = threadIdx.x;              // 0..127
    const int tx  = tid & 15;
    const int qy  = tid >> 4;                 // 0..7 -> output rows 4qy..4qy+3
    const int gx0 = blockIdx.x * TW;
    const int gy0 = blockIdx.y * TH;
    const int bz  = blockIdx.z;

    const float* xb = x + (size_t)bz * ((size_t)HH * WW * CC);
    unsigned smem_base = (unsigned)__cvta_generic_to_shared(tile4);

    // ---- stage w2/b2 into smem ----
    #pragma unroll
    for (int i = tid; i < W2_F4; i += 128) w2s[i] = scratchW.w2[i];
    if (tid < B2_F4) b2s[tid] = scratchW.b2[tid];

    // ---- tile half u0-7 (channels 0..31), zero-fill OOB ----
    for (int s = tid; s < NPX * 8; s += 128) {
        int u   = s & 7;
        int pix = s >> 3;
        int py  = pix / HW;
        int px  = pix - py * HW;
        int gh  = gy0 - 1 + py;
        int gw  = gx0 - 1 + px;
        bool ok = ((unsigned)gh < HH) && ((unsigned)gw < WW);
        const float4* src = (const float4*)(xb + ((size_t)(ok ? gh : 0) * WW + (ok ? gw : 0)) * CC) + u;
        cp16(smem_base + (unsigned)(pix * PSTR + u) * 16u, src, ok ? 16 : 0);
    }
    asm volatile("cp.async.commit_group;\n\tcp.async.wait_group 0;" ::: "memory");
    __syncthreads();

    // ---- phase B: t2[p][dp] = x_p . w1' + b1' (packed d-pairs), 4 pixels ----
    const float4* xc[4];
    const float4* gp[4];
    #pragma unroll
    for (int p = 0; p < 4; p++) {
        xc[p] = tile4 + ((4 * qy + p + 1) * HW + (tx + 1)) * PSTR;
        gp[p] = (const float4*)(xb + ((size_t)(gy0 + 4 * qy + p) * WW + gx0 + tx) * CC);
    }

    u64 t2[4][8];
    #pragma unroll
    for (int dp = 0; dp < 8; dp++) {
        u64 b = cW.b1p[dp];
        t2[0][dp] = b; t2[1][dp] = b; t2[2][dp] = b; t2[3][dp] = b;
    }

    #pragma unroll 2
    for (int c4 = 0; c4 < 8; c4++) {               // first channel half from smem
        u64 xd[4][4];
        #pragma unroll
        for (int p = 0; p < 4; p++) {
            float4 xv = xc[p][c4];
            xd[p][0] = dup2(xv.x); xd[p][1] = dup2(xv.y);
            xd[p][2] = dup2(xv.z); xd[p][3] = dup2(xv.w);
        }
        #pragma unroll
        for (int dp = 0; dp < 8; dp++) {
            const u64* w = cW.w1p[c4][dp];
            #pragma unroll
            for (int p = 0; p < 4; p++) {
                u64 acc = t2[p][dp];
                acc = fma2(xd[p][0], w[0], acc);
                acc = fma2(xd[p][1], w[1], acc);
                acc = fma2(xd[p][2], w[2], acc);
                acc = fma2(xd[p][3], w[3], acc);
                t2[p][dp] = acc;
            }
        }
    }
    #pragma unroll 2
    for (int c4 = 8; c4 < 16; c4++) {              // second channel half from global
        u64 xd[4][4];
        #pragma unroll
        for (int p = 0; p < 4; p++) {
            float4 xv = gp[p][c4];
            xd[p][0] = dup2(xv.x); xd[p][1] = dup2(xv.y);
            xd[p][2] = dup2(xv.z); xd[p][3] = dup2(xv.w);
        }
        #pragma unroll
        for (int dp = 0; dp < 8; dp++) {
            const u64* w = cW.w1p[c4][dp];
            #pragma unroll
            for (int p = 0; p < 4; p++) {
                u64 acc = t2[p][dp];
                acc = fma2(xd[p][0], w[0], acc);
                acc = fma2(xd[p][1], w[1], acc);
                acc = fma2(xd[p][2], w[2], acc);
                acc = fma2(xd[p][3], w[3], acc);
                t2[p][dp] = acc;
            }
        }
    }

    // unpack + relu -> scalar t[4][16]
    float t[4][CR];
    #pragma unroll
    for (int p = 0; p < 4; p++) {
        #pragma unroll
        for (int dp = 0; dp < 8; dp++) {
            float2 f = unpk(t2[p][dp]);
            t[p][2 * dp]     = fmaxf(f.x, 0.f);
            t[p][2 * dp + 1] = fmaxf(f.y, 0.f);
        }
    }

    // ---- phase C: two sequential pixel-pairs, packed group-pairs ----
    u64 k2[4][TAPS][2];
    const ulonglong2* w2p = (const ulonglong2*)w2s;
    const ulonglong2* b2p = (const ulonglong2*)b2s;
    #pragma unroll
    for (int pp = 0; pp < 2; pp++) {
        const int p0 = 2 * pp, p1 = 2 * pp + 1;
        #pragma unroll
        for (int tap = 0; tap < TAPS; tap++) {
            ulonglong2 b = b2p[tap];
            k2[p0][tap][0] = b.x; k2[p0][tap][1] = b.y;
            k2[p1][tap][0] = b.x; k2[p1][tap][1] = b.y;
        }
        #pragma unroll
        for (int d = 0; d < CR; d++) {
            u64 a0 = dup2(t[p0][d]);
            u64 a1 = dup2(t[p1][d]);
            #pragma unroll
            for (int tap = 0; tap < TAPS; tap++) {
                ulonglong2 w = w2p[d * TAPS + tap];
                k2[p0][tap][0] = fma2(a0, w.x, k2[p0][tap][0]);
                k2[p0][tap][1] = fma2(a0, w.y, k2[p0][tap][1]);
                k2[p1][tap][0] = fma2(a1, w.x, k2[p1][tap][0]);
                k2[p1][tap][1] = fma2(a1, w.y, k2[p1][tap][1]);
            }
        }
    }

    // ---- phase D ----
    ulonglong2* o[4];
    #pragma unroll
    for (int p = 0; p < 4; p++)
        o[p] = (ulonglong2*)(out + (((size_t)bz * HH + gy0 + 4 * qy + p) * WW + gx0 + tx) * CC);
    const int rowstep = HW * PSTR;
    const float4* base = tile4 + (4 * qy * HW + tx) * PSTR;

    // pass 0: planes u0-7 (channels 0..31); after each plane, reload its slot
    // with channel-plane 8+u via cp.async (overlaps remaining pass-0 compute)
    #pragma unroll
    for (int u = 0; u < 8; u++) {
        u64 a[4][2];
        #pragma unroll
        for (int p = 0; p < 4; p++) { a[p][0] = 0; a[p][1] = 0; }
        #pragma unroll
        for (int dj = 0; dj < 3; dj++) {
            const float4* col = base + dj * PSTR + u;
            ulonglong2 r0 = *(const ulonglong2*)(col);
            ulonglong2 r1 = *(const ulonglong2*)(col + rowstep);
            ulonglong2 r2 = *(const ulonglong2*)(col + 2 * rowstep);
            ulonglong2 r3 = *(const ulonglong2*)(col + 3 * rowstep);
            ulonglong2 r4 = *(const ulonglong2*)(col + 4 * rowstep);
            ulonglong2 r5 = *(const ulonglong2*)(col + 5 * rowstep);
            a[0][0] = fma2(k2[0][dj][0],     r0.x, a[0][0]);
            a[0][1] = fma2(k2[0][dj][1],     r0.y, a[0][1]);
            a[0][0] = fma2(k2[0][3 + dj][0], r1.x, a[0][0]);
            a[0][1] = fma2(k2[0][3 + dj][1], r1.y, a[0][1]);
            a[0][0] = fma2(k2[0][6 + dj][0], r2.x, a[0][0]);
            a[0][1] = fma2(k2[0][6 + dj][1], r2.y, a[0][1]);
            a[1][0] = fma2(k2[1][dj][0],     r1.x, a[1][0]);
            a[1][1] = fma2(k2[1][dj][1],     r1.y, a[1][1]);
            a[1][0] = fma2(k2[1][3 + dj][0], r2.x, a[1][0]);
            a[1][1] = fma2(k2[1][3 + dj][1], r2.y, a[1][1]);
            a[1][0] = fma2(k2[1][6 + dj][0], r3.x, a[1][0]);
            a[1][1] = fma2(k2[1][6 + dj][1], r3.y, a[1][1]);
            a[2][0] = fma2(k2[2][dj][0],     r2.x, a[2][0]);
            a[2][1] = fma2(k2[2][dj][1],     r2.y, a[2][1]);
            a[2][0] = fma2(k2[2][3 + dj][0], r3.x, a[2][0]);
            a[2][1] = fma2(k2[2][3 + dj][1], r3.y, a[2][1]);
            a[2][0] = fma2(k2[2][6 + dj][0], r4.x, a[2][0]);
            a[2][1] = fma2(k2[2][6 + dj][1], r4.y, a[2][1]);
            a[3][0] = fma2(k2[3][dj][0],     r3.x, a[3][0]);
            a[3][1] = fma2(k2[3][dj][1],     r3.y, a[3][1]);
            a[3][0] = fma2(k2[3][3 + dj][0], r4.x, a[3][0]);
            a[3][1] = fma2(k2[3][3 + dj][1], r4.y, a[3][1]);
            a[3][0] = fma2(k2[3][6 + dj][0], r5.x, a[3][0]);
            a[3][1] = fma2(k2[3][6 + dj][1], r5.y, a[3][1]);
        }
        #pragma unroll
        for (int p = 0; p < 4; p++) {
            ulonglong2 v;
            v.x = a[p][0]; v.y = a[p][1];
            o[p][u] = v;
        }

        // plane u fully consumed by all threads -> reload it with channel 8+u
        __syncthreads();
        for (int s = tid; s < NPX; s += 128) {
            int py = s / HW;
            int px = s - py * HW;
            int gh = gy0 - 1 + py;
            int gw = gx0 - 1 + px;
            bool ok = ((unsigned)gh < HH) && ((unsigned)gw < WW);
            const float4* src = (const float4*)(xb + ((size_t)(ok ? gh : 0) * WW + (ok ? gw : 0)) * CC)
                                + 8 + u;
            cp16(smem_base + (unsigned)(s * PSTR + u) * 16u, src, ok ? 16 : 0);
        }
        asm volatile("cp.async.commit_group;" ::: "memory");
    }

    asm volatile("cp.async.wait_group 0;" ::: "memory");
    __syncthreads();

    // pass 1: planes u0-7 now hold channels 32..63
    #pragma unroll
    for (int u = 0; u < 8; u++) {
        u64 a[4][2];
        #pragma unroll
        for (int p = 0; p < 4; p++) { a[p][0] = 0; a[p][1] = 0; }
        #pragma unroll
        for (int dj = 0; dj < 3; dj++) {
            const float4* col = base + dj * PSTR + u;
            ulonglong2 r0 = *(const ulonglong2*)(col);
            ulonglong2 r1 = *(const ulonglong2*)(col + rowstep);
            ulonglong2 r2 = *(const ulonglong2*)(col + 2 * rowstep);
            ulonglong2 r3 = *(const ulonglong2*)(col + 3 * rowstep);
            ulonglong2 r4 = *(const ulonglong2*)(col + 4 * rowstep);
            ulonglong2 r5 = *(const ulonglong2*)(col + 5 * rowstep);
            a[0][0] = fma2(k2[0][dj][0],     r0.x, a[0][0]);
            a[0][1] = fma2(k2[0][dj][1],     r0.y, a[0][1]);
            a[0][0] = fma2(k2[0][3 + dj][0], r1.x, a[0][0]);
            a[0][1] = fma2(k2[0][3 + dj][1], r1.y, a[0][1]);
            a[0][0] = fma2(k2[0][6 + dj][0], r2.x, a[0][0]);
            a[0][1] = fma2(k2[0][6 + dj][1], r2.y, a[0][1]);
            a[1][0] = fma2(k2[1][dj][0],     r1.x, a[1][0]);
            a[1][1] = fma2(k2[1][dj][1],     r1.y, a[1][1]);
            a[1][0] = fma2(k2[1][3 + dj][0], r2.x, a[1][0]);
            a[1][1] = fma2(k2[1][3 + dj][1], r2.y, a[1][1]);
            a[1][0] = fma2(k2[1][6 + dj][0], r3.x, a[1][0]);
            a[1][1] = fma2(k2[1][6 + dj][1], r3.y, a[1][1]);
            a[2][0] = fma2(k2[2][dj][0],     r2.x, a[2][0]);
            a[2][1] = fma2(k2[2][dj][1],     r2.y, a[2][1]);
            a[2][0] = fma2(k2[2][3 + dj][0], r3.x, a[2][0]);
            a[2][1] = fma2(k2[2][3 + dj][1], r3.y, a[2][1]);
            a[2][0] = fma2(k2[2][6 + dj][0], r4.x, a[2][0]);
            a[2][1] = fma2(k2[2][6 + dj][1], r4.y, a[2][1]);
            a[3][0] = fma2(k2[3][dj][0],     r3.x, a[3][0]);
            a[3][1] = fma2(k2[3][dj][1],     r3.y, a[3][1]);
            a[3][0] = fma2(k2[3][3 + dj][0], r4.x, a[3][0]);
            a[3][1] = fma2(k2[3][3 + dj][1], r4.y, a[3][1]);
            a[3][0] = fma2(k2[3][6 + dj][0], r5.x, a[3][0]);
            a[3][1] = fma2(k2[3][6 + dj][1], r5.y, a[3][1]);
        }
        #pragma unroll
        for (int p = 0; p < 4; p++) {
            ulonglong2 v;
            v.x = a[p][0]; v.y = a[p][1];
            o[p][8 + u] = v;
        }
    }
}

extern "C" void kernel_launch(void* const* d_in, const int* in_sizes, int n_in,
                              void* d_out, int out_size) {
    const float* x     = (const float*)d_in[0];
    const float* w1    = (const float*)d_in[1];
    const float* b1    = (const float*)d_in[2];
    const float* gamma = (const float*)d_in[3];
    const float* beta  = (const float*)d_in[4];
    const float* mean  = (const float*)d_in[5];
    const float* var   = (const float*)d_in[6];
    const float* w2    = (const float*)d_in[7];
    const float* b2    = (const float*)d_in[8];
    float* out = (float*)d_out;

    int B = in_sizes[0] / (HH * WW * CC);

    // 1) fold BN + pack weights
    involution_prep_kernel<<<1, 256>>>(w1, b1, gamma, beta, mean, var, w2, b2);

    // 2) copy packed w1/b1 into __constant__ (D2D memcpy node, capturable)
    static char* scratch_addr = nullptr;
    if (!scratch_addr) cudaGetSymbolAddress((void**)&scratch_addr, scratchW);
    cudaMemcpyToSymbolAsync(cW, scratch_addr + offsetof(Scratch, c),
                            sizeof(ConstW), 0, cudaMemcpyDeviceToDevice, 0);

    // 3) main fused kernel
    static bool attr_set = false;
    if (!attr_set) {
        cudaFuncSetAttribute(involution_fused_kernel,
                             cudaFuncAttributeMaxDynamicSharedMemorySize, SMEM_BYTES);
        attr_set = true;
    }
    dim3 grid(WW / TW, HH / TH, B);   // 12 x 6 x 8
    involution_fused_kernel<<<grid, 128, SMEM_BYTES>>>(x, out);
}